// round 15
// baseline (speedup 1.0000x reference)
#include <cuda_runtime.h>
#include <cstdint>

#define NN    50000
#define EE    800000
#define ETOT  (EE + NN)
#define DIN_  128
#define MT_PAD 3128                 // ceil(50000/16) 16-row tiles
#define KC16   16                   // K/8 k-chunks
#define AWORDS (MT_PAD * KC16 * 32) // uint4 count per frag matrix

// ---------------- scratch (device globals: no runtime allocation) ----------
__device__ float g_xl[(size_t)NN * DIN_];
__device__ float g_xr[(size_t)NN * DIN_];
__device__ float g_h [(size_t)NN * DIN_];
__device__ int   g_es[ETOT];
__device__ int   g_hist[NN];
__device__ int   g_cnt[NN];
__device__ int   g_rowstart[NN + 1];
__device__ int   g_bsum[64];
__device__ int   g_boff[64];
__device__ int   g_is32;

// fragment-major tf32 hi/lo A buffers: uint4 at ((mt*16 + kc)*32 + lane)
__device__ uint4 g_xfh[AWORDS],  g_xfl[AWORDS];    // x
__device__ uint4 g_hfh[AWORDS],  g_hfl[AWORDS];    // h   (aconv<2>)
__device__ uint4 g_h1fh[AWORDS], g_h1fl[AWORDS];   // h1  (epilogue-emitted)
// fragment-major tf32 weights: uint2 at woff + (kc*NT + nt)*32 + lane
// Wl=0, Wr=8192, W1=16384, W2=24576, W3=32768
__device__ uint2 g_wfh[36864], g_wfl[36864];

__device__ __forceinline__ const uint4* abuf_h(int id) {
    switch (id) { case 2: return g_hfh; default: return g_h1fh; }
}
__device__ __forceinline__ const uint4* abuf_l(int id) {
    switch (id) { case 2: return g_hfl; default: return g_h1fl; }
}

// ---------------- helpers ----------------------------------------------------
__device__ __forceinline__ float lrelu(float v) { return v > 0.f ? v : 0.2f * v; }

__device__ __forceinline__ float warp_sum(float v) {
#pragma unroll
    for (int o = 16; o > 0; o >>= 1) v += __shfl_xor_sync(0xffffffffu, v, o);
    return v;
}

__device__ __forceinline__ int edge_at(const void* ei, long long idx) {
    if (g_is32) return ((const int*)ei)[idx];
    return (int)((const long long*)ei)[idx];
}

__device__ __forceinline__ uint32_t f2tf32(float x) {
    uint32_t r;
    asm("cvt.rna.tf32.f32 %0, %1;" : "=r"(r) : "f"(x));
    return r;
}
__device__ __forceinline__ void tf32_split(float x, uint32_t& hi, uint32_t& lo) {
    hi = f2tf32(x);
    lo = f2tf32(x - __uint_as_float(hi));
}

__device__ __forceinline__ void mma_tf32(float* d, const uint32_t* a,
                                         const uint32_t* b) {
    asm volatile(
        "mma.sync.aligned.m16n8k8.row.col.f32.tf32.tf32.f32 "
        "{%0,%1,%2,%3}, {%4,%5,%6,%7}, {%8,%9}, {%0,%1,%2,%3};"
        : "+f"(d[0]), "+f"(d[1]), "+f"(d[2]), "+f"(d[3])
        : "r"(a[0]), "r"(a[1]), "r"(a[2]), "r"(a[3]), "r"(b[0]), "r"(b[1]));
}

__device__ __forceinline__ void cp_async16(uint32_t dst, const void* src) {
    asm volatile("cp.async.cg.shared.global [%0], [%1], 16;"
                 :: "r"(dst), "l"(src));
}
__device__ __forceinline__ void cp_commit() {
    asm volatile("cp.async.commit_group;");
}
__device__ __forceinline__ void cp_wait0() {
    asm volatile("cp.async.wait_group 0;");
}
__device__ __forceinline__ void cp_wait1() {
    asm volatile("cp.async.wait_group 1;");
}

// ---------------- all-weights convert + edge dtype detect (one launch) ------
__global__ void wconv_all(const float* __restrict__ Wl,
                          const float* __restrict__ Wr,
                          const float* __restrict__ W1,
                          const float* __restrict__ W2,
                          const float* __restrict__ W3,
                          const unsigned long long* __restrict__ ei, int m)
{
    int bx = blockIdx.x;
    if (bx == 72) {   // edge dtype detection
        __shared__ int found;
        if (threadIdx.x == 0) found = 0;
        __syncthreads();
        for (int i = threadIdx.x; i < m; i += blockDim.x)
            if ((ei[i] >> 32) != 0ull) found = 1;
        __syncthreads();
        if (threadIdx.x == 0) g_is32 = found;
        return;
    }
    const float* W;
    int woff, nt, M = 128;
    if      (bx < 16) { W = Wl; woff = 0;     nt = bx; }
    else if (bx < 32) { W = Wr; woff = 8192;  nt = bx - 16; }
    else if (bx < 48) { W = W1; woff = 16384; nt = bx - 32; }
    else if (bx < 64) { W = W2; woff = 24576; nt = bx - 48; }
    else              { W = W3; woff = 32768; nt = bx - 64; M = 64; }
    int NT = M / 8;
    int tid = threadIdx.x;
    int w8 = tid >> 5, lane = tid & 31, g = lane >> 2, tig = lane & 3;
    int ncol = nt * 8 + g;
#pragma unroll
    for (int j = 0; j < 2; j++) {
        int kc = w8 + j * 8;
        int k0 = kc * 8 + tig;
        float w0 = W[(size_t)k0 * M + ncol];
        float w1 = W[(size_t)(k0 + 4) * M + ncol];
        uint32_t h0, l0, h1, l1;
        tf32_split(w0, h0, l0);
        tf32_split(w1, h1, l1);
        int ix = woff + (kc * NT + nt) * 32 + lane;
        g_wfh[ix] = make_uint2(h0, h1);
        g_wfl[ix] = make_uint2(l0, l1);
    }
}

// ---------------- activation convert (+ optional fused histogram) -----------
// SRC=1: x -> xf, blocks >= MT_PAD run edge histogram. SRC=2: g_h -> hf.
template<int SRC>
__global__ __launch_bounds__(256)
void aconv_kernel(const float* __restrict__ Xp, int n,
                  const void* __restrict__ ei, int E, int et)
{
    if (SRC == 1 && blockIdx.x >= MT_PAD) {
        int e = (blockIdx.x - MT_PAD) * 256 + threadIdx.x;
        if (e < et) {
            int d = (e < E) ? edge_at(ei, (long long)E + e) : (e - E);
            d = min(max(d, 0), n - 1);
            atomicAdd(&g_hist[d], 1);
        }
        return;
    }
    const float* X = (SRC == 1) ? Xp : g_h;
    __shared__ float s[16 * 132];
    int mt = blockIdx.x;
    int tid = threadIdx.x;
#pragma unroll
    for (int j = 0; j < 2; j++) {
        int f = tid + j * 256;
        int row = f >> 5;
        int q = f & 31;
        int r = mt * 16 + row;
        float4 v = (r < n) ? *(const float4*)(X + (size_t)r * 128 + q * 4)
                           : make_float4(0.f, 0.f, 0.f, 0.f);
        *(float4*)&s[row * 132 + q * 4] = v;
    }
    __syncthreads();

    int w8 = tid >> 5, lane = tid & 31, g = lane >> 2, tig = lane & 3;
    uint4* OH = (SRC == 1) ? g_xfh : g_hfh;
    uint4* OL = (SRC == 1) ? g_xfl : g_hfl;
#pragma unroll
    for (int j = 0; j < 2; j++) {
        int kc = w8 + j * 8;
        int c0 = kc * 8 + tig, c1 = c0 + 4;
        float p0 = s[g * 132 + c0];
        float p1 = s[(g + 8) * 132 + c0];
        float p2 = s[g * 132 + c1];
        float p3 = s[(g + 8) * 132 + c1];
        uint4 H, L;
        tf32_split(p0, H.x, L.x);
        tf32_split(p1, H.y, L.y);
        tf32_split(p2, H.z, L.z);
        tf32_split(p3, H.w, L.w);
        int ix = (mt * KC16 + kc) * 32 + lane;
        OH[ix] = H;
        OL[ix] = L;
    }
}

// ---------------- fused xl+xr GEMM (2-stage, tail-merged; R14-validated) ----
__global__ __launch_bounds__(256)
void gemm_xlr(const float* __restrict__ bl, const float* __restrict__ br,
              int gm, int n)
{
    constexpr int NT = 16, NTW = 8, B4 = 256;

    const bool isR = blockIdx.x >= gm;
    const int  bx  = isR ? (blockIdx.x - gm) : blockIdx.x;
    const int  woff = isR ? 8192 : 0;
    float* out = isR ? g_xr : g_xl;
    const float* bias = isR ? br : bl;

    const uint4* AH = g_xfh;
    const uint4* AL = g_xfl;
    const uint2* BH = g_wfh + woff;
    const uint2* BL = g_wfl + woff;

    __shared__ uint4 sAh[2][256], sAl[2][256];
    __shared__ uint4 sBh[2][B4],  sBl[2][B4];

    const int tid   = threadIdx.x;
    const int lane  = tid & 31;
    const int wid   = tid >> 5;
    const int warpM = wid & 3;
    const int warpN = wid >> 2;
    const int mtb   = bx * 8;

    const int a_mt = tid >> 5;
    const int a_ln = tid & 31;

#define ISSUE_STAGE(KC_, BUF_)                                                  \
    do {                                                                        \
        int _src = ((mtb + a_mt) * KC16 + (KC_)) * 32 + a_ln;                  \
        cp_async16((uint32_t)__cvta_generic_to_shared(&sAh[BUF_][tid]),        \
                   AH + _src);                                                  \
        cp_async16((uint32_t)__cvta_generic_to_shared(&sAl[BUF_][tid]),        \
                   AL + _src);                                                  \
        const uint4* _bh = (const uint4*)(BH + (size_t)(KC_) * NT * 32);       \
        const uint4* _bl = (const uint4*)(BL + (size_t)(KC_) * NT * 32);       \
        cp_async16((uint32_t)__cvta_generic_to_shared(&sBh[BUF_][tid]),        \
                   _bh + tid);                                                  \
        cp_async16((uint32_t)__cvta_generic_to_shared(&sBl[BUF_][tid]),        \
                   _bl + tid);                                                  \
        cp_commit();                                                            \
    } while (0)

    float acc[2][NTW][4];
#pragma unroll
    for (int m = 0; m < 2; m++)
#pragma unroll
        for (int t = 0; t < NTW; t++)
#pragma unroll
            for (int i = 0; i < 4; i++) acc[m][t][i] = 0.f;

    ISSUE_STAGE(0, 0);

#pragma unroll 2
    for (int kc = 0; kc < KC16; kc++) {
        const int buf = kc & 1;
        if (kc + 1 < KC16) {
            ISSUE_STAGE(kc + 1, buf ^ 1);
            cp_wait1();
        } else {
            cp_wait0();
        }
        __syncthreads();

        uint4 ah[2], al[2];
#pragma unroll
        for (int m = 0; m < 2; m++) {
            int ix = (warpM * 2 + m) * 32 + lane;
            ah[m] = sAh[buf][ix];
            al[m] = sAl[buf][ix];
        }
        const uint2* b2h = (const uint2*)sBh[buf];
        const uint2* b2l = (const uint2*)sBl[buf];
#pragma unroll
        for (int t = 0; t < NTW; t++) {
            int nt = warpN * NTW + t;
            uint2 bh = b2h[nt * 32 + lane];
            uint2 bl2 = b2l[nt * 32 + lane];
#pragma unroll
            for (int m = 0; m < 2; m++) {
                mma_tf32(acc[m][t], (const uint32_t*)&al[m],
                         (const uint32_t*)&bh);
                mma_tf32(acc[m][t], (const uint32_t*)&ah[m],
                         (const uint32_t*)&bl2);
                mma_tf32(acc[m][t], (const uint32_t*)&ah[m],
                         (const uint32_t*)&bh);
            }
        }
        __syncthreads();
    }
#undef ISSUE_STAGE

    const int g   = lane >> 2;
    const int tig = lane & 3;
#pragma unroll
    for (int m = 0; m < 2; m++) {
#pragma unroll
        for (int t = 0; t < NTW; t++) {
            int row = (mtb + warpM * 2 + m) * 16 + g;
            int col = (warpN * NTW + t) * 8 + tig * 2;
            float b0 = bias[col], b1 = bias[col + 1];
            float d0 = acc[m][t][0] + b0, d1 = acc[m][t][1] + b1;
            float d2 = acc[m][t][2] + b0, d3 = acc[m][t][3] + b1;
            if (row < n)
                *(float2*)(out + (size_t)row * 128 + col) = make_float2(d0, d1);
            if (row + 8 < n)
                *(float2*)(out + (size_t)(row + 8) * 128 + col) =
                    make_float2(d2, d3);
        }
    }
}

// ---------------- h -> h1 GEMM with frag-direct emission (R10-validated) ----
__global__ __launch_bounds__(256)
void gemm_h1(const float* __restrict__ bias, int woff, int n)
{
    constexpr int NT = 16, NTW = 8, B4 = 256;

    const uint4* AH = g_hfh;
    const uint4* AL = g_hfl;
    const uint2* BH = g_wfh + woff;
    const uint2* BL = g_wfl + woff;

    __shared__ uint4 sAh[2][256], sAl[2][256];
    __shared__ uint4 sBh[2][B4],  sBl[2][B4];

    const int tid   = threadIdx.x;
    const int lane  = tid & 31;
    const int wid   = tid >> 5;
    const int warpM = wid & 3;
    const int warpN = wid >> 2;
    const int mtb   = blockIdx.x * 8;

    const int a_mt = tid >> 5;
    const int a_ln = tid & 31;

#define ISSUE_STAGE(KC_, BUF_)                                                  \
    do {                                                                        \
        int _src = ((mtb + a_mt) * KC16 + (KC_)) * 32 + a_ln;                  \
        cp_async16((uint32_t)__cvta_generic_to_shared(&sAh[BUF_][tid]),        \
                   AH + _src);                                                  \
        cp_async16((uint32_t)__cvta_generic_to_shared(&sAl[BUF_][tid]),        \
                   AL + _src);                                                  \
        const uint4* _bh = (const uint4*)(BH + (size_t)(KC_) * NT * 32);       \
        const uint4* _bl = (const uint4*)(BL + (size_t)(KC_) * NT * 32);       \
        cp_async16((uint32_t)__cvta_generic_to_shared(&sBh[BUF_][tid]),        \
                   _bh + tid);                                                  \
        cp_async16((uint32_t)__cvta_generic_to_shared(&sBl[BUF_][tid]),        \
                   _bl + tid);                                                  \
        cp_commit();                                                            \
    } while (0)

    float acc[2][NTW][4];
#pragma unroll
    for (int m = 0; m < 2; m++)
#pragma unroll
        for (int t = 0; t < NTW; t++)
#pragma unroll
            for (int i = 0; i < 4; i++) acc[m][t][i] = 0.f;

    ISSUE_STAGE(0, 0);

#pragma unroll 2
    for (int kc = 0; kc < KC16; kc++) {
        const int buf = kc & 1;
        if (kc + 1 < KC16) {
            ISSUE_STAGE(kc + 1, buf ^ 1);
            cp_wait1();
        } else {
            cp_wait0();
        }
        __syncthreads();

        uint4 ah[2], al[2];
#pragma unroll
        for (int m = 0; m < 2; m++) {
            int ix = (warpM * 2 + m) * 32 + lane;
            ah[m] = sAh[buf][ix];
            al[m] = sAl[buf][ix];
        }
        const uint2* b2h = (const uint2*)sBh[buf];
        const uint2* b2l = (const uint2*)sBl[buf];
#pragma unroll
        for (int t = 0; t < NTW; t++) {
            int nt = warpN * NTW + t;
            uint2 bh = b2h[nt * 32 + lane];
            uint2 bl = b2l[nt * 32 + lane];
#pragma unroll
            for (int m = 0; m < 2; m++) {
                mma_tf32(acc[m][t], (const uint32_t*)&al[m],
                         (const uint32_t*)&bh);
                mma_tf32(acc[m][t], (const uint32_t*)&ah[m],
                         (const uint32_t*)&bl);
                mma_tf32(acc[m][t], (const uint32_t*)&ah[m],
                         (const uint32_t*)&bh);
            }
        }
        __syncthreads();
    }
#undef ISSUE_STAGE

    const int g   = lane >> 2;
    const int tig = lane & 3;
    const int srcA = (lane & ~3) + (tig >> 1);
    const int srcB = srcA + 2;
    const bool oddc = (tig & 1) != 0;
#pragma unroll
    for (int m = 0; m < 2; m++) {
        int mtg = mtb + warpM * 2 + m;
#pragma unroll
        for (int t = 0; t < NTW; t++) {
            int kc  = warpN * NTW + t;
            int col = kc * 8 + tig * 2;
            float b0 = bias[col], b1 = bias[col + 1];
            float d0 = fmaxf(acc[m][t][0] + b0, 0.f);
            float d1 = fmaxf(acc[m][t][1] + b1, 0.f);
            float d2 = fmaxf(acc[m][t][2] + b0, 0.f);
            float d3 = fmaxf(acc[m][t][3] + b1, 0.f);
            float s0 = __shfl_sync(0xffffffffu, d0, srcA);
            float s1 = __shfl_sync(0xffffffffu, d1, srcA);
            float a0 = oddc ? s1 : s0;
            float s2 = __shfl_sync(0xffffffffu, d2, srcA);
            float s3 = __shfl_sync(0xffffffffu, d3, srcA);
            float a1 = oddc ? s3 : s2;
            float s4 = __shfl_sync(0xffffffffu, d0, srcB);
            float s5 = __shfl_sync(0xffffffffu, d1, srcB);
            float a2 = oddc ? s5 : s4;
            float s6 = __shfl_sync(0xffffffffu, d2, srcB);
            float s7 = __shfl_sync(0xffffffffu, d3, srcB);
            float a3 = oddc ? s7 : s6;
            uint4 H, L;
            tf32_split(a0, H.x, L.x);
            tf32_split(a1, H.y, L.y);
            tf32_split(a2, H.z, L.z);
            tf32_split(a3, H.w, L.w);
            int ix = (mtg * KC16 + kc) * 32 + lane;
            g_h1fh[ix] = H;
            g_h1fl[ix] = L;
        }
    }
}

// ---------------- FUSED h2 + out GEMM ----------------------------------------
// h2 = relu(h1 @ W2 + b2) computed in registers (same validated main loop);
// then out = h2 @ W3 + b3 via per-kc smem frag exchange (shuffle emission
// into sAh[0]/sAl[0], W3 B-frags direct LDG from L2-resident g_wfh+32768).
__global__ __launch_bounds__(256, 2)
void gemm_h2out(float* __restrict__ out, const float* __restrict__ bias2,
                const float* __restrict__ bias3, int n)
{
    constexpr int NT = 16, NTW = 8, B4 = 256;

    const uint4* AH = g_h1fh;
    const uint4* AL = g_h1fl;
    const uint2* BH = g_wfh + 24576;    // W2
    const uint2* BL = g_wfl + 24576;

    __shared__ uint4 sAh[2][256], sAl[2][256];
    __shared__ uint4 sBh[2][B4],  sBl[2][B4];

    const int tid   = threadIdx.x;
    const int lane  = tid & 31;
    const int wid   = tid >> 5;
    const int warpM = wid & 3;
    const int warpN = wid >> 2;
    const int mtb   = blockIdx.x * 8;

    const int a_mt = tid >> 5;
    const int a_ln = tid & 31;

#define ISSUE_STAGE(KC_, BUF_)                                                  \
    do {                                                                        \
        int _src = ((mtb + a_mt) * KC16 + (KC_)) * 32 + a_ln;                  \
        cp_async16((uint32_t)__cvta_generic_to_shared(&sAh[BUF_][tid]),        \
                   AH + _src);                                                  \
        cp_async16((uint32_t)__cvta_generic_to_shared(&sAl[BUF_][tid]),        \
                   AL + _src);                                                  \
        const uint4* _bh = (const uint4*)(BH + (size_t)(KC_) * NT * 32);       \
        const uint4* _bl = (const uint4*)(BL + (size_t)(KC_) * NT * 32);       \
        cp_async16((uint32_t)__cvta_generic_to_shared(&sBh[BUF_][tid]),        \
                   _bh + tid);                                                  \
        cp_async16((uint32_t)__cvta_generic_to_shared(&sBl[BUF_][tid]),        \
                   _bl + tid);                                                  \
        cp_commit();                                                            \
    } while (0)

    float acc[2][NTW][4];
#pragma unroll
    for (int m = 0; m < 2; m++)
#pragma unroll
        for (int t = 0; t < NTW; t++)
#pragma unroll
            for (int i = 0; i < 4; i++) acc[m][t][i] = 0.f;

    ISSUE_STAGE(0, 0);

#pragma unroll 2
    for (int kc = 0; kc < KC16; kc++) {
        const int buf = kc & 1;
        if (kc + 1 < KC16) {
            ISSUE_STAGE(kc + 1, buf ^ 1);
            cp_wait1();
        } else {
            cp_wait0();
        }
        __syncthreads();

        uint4 ah[2], al[2];
#pragma unroll
        for (int m = 0; m < 2; m++) {
            int ix = (warpM * 2 + m) * 32 + lane;
            ah[m] = sAh[buf][ix];
            al[m] = sAl[buf][ix];
        }
        const uint2* b2h = (const uint2*)sBh[buf];
        const uint2* b2l = (const uint2*)sBl[buf];
#pragma unroll
        for (int t = 0; t < NTW; t++) {
            int nt = warpN * NTW + t;
            uint2 bh = b2h[nt * 32 + lane];
            uint2 bl = b2l[nt * 32 + lane];
#pragma unroll
            for (int m = 0; m < 2; m++) {
                mma_tf32(acc[m][t], (const uint32_t*)&al[m],
                         (const uint32_t*)&bh);
                mma_tf32(acc[m][t], (const uint32_t*)&ah[m],
                         (const uint32_t*)&bl);
                mma_tf32(acc[m][t], (const uint32_t*)&ah[m],
                         (const uint32_t*)&bh);
            }
        }
        __syncthreads();
    }
#undef ISSUE_STAGE

    // ---- fused: out = h2 @ W3 + b3 (K=128, N=64), h2 routed via smem ----
    const int g   = lane >> 2;
    const int tig = lane & 3;
    const int srcA = (lane & ~3) + (tig >> 1);
    const int srcB = srcA + 2;
    const bool oddc = (tig & 1) != 0;

    const uint2* B3H = g_wfh + 32768;
    const uint2* B3L = g_wfl + 32768;

    float oacc[2][4][4];
#pragma unroll
    for (int m = 0; m < 2; m++)
#pragma unroll
        for (int t = 0; t < 4; t++)
#pragma unroll
            for (int i = 0; i < 4; i++) oacc[m][t][i] = 0.f;

    for (int kc = 0; kc < KC16; kc++) {
        if ((kc >> 3) == warpN) {       // this warp group owns kc: emit frags
            int t = kc & 7;
            int col = kc * 8 + tig * 2;
            float b0 = bias2[col], b1 = bias2[col + 1];
#pragma unroll
            for (int m = 0; m < 2; m++) {
                float d0 = fmaxf(acc[m][t][0] + b0, 0.f);
                float d1 = fmaxf(acc[m][t][1] + b1, 0.f);
                float d2 = fmaxf(acc[m][t][2] + b0, 0.f);
                float d3 = fmaxf(acc[m][t][3] + b1, 0.f);
                float s0 = __shfl_sync(0xffffffffu, d0, srcA);
                float s1 = __shfl_sync(0xffffffffu, d1, srcA);
                float a0 = oddc ? s1 : s0;
                float s2 = __shfl_sync(0xffffffffu, d2, srcA);
                float s3 = __shfl_sync(0xffffffffu, d3, srcA);
                float a1 = oddc ? s3 : s2;
                float s4 = __shfl_sync(0xffffffffu, d0, srcB);
                float s5 = __shfl_sync(0xffffffffu, d1, srcB);
                float a2 = oddc ? s5 : s4;
                float s6 = __shfl_sync(0xffffffffu, d2, srcB);
                float s7 = __shfl_sync(0xffffffffu, d3, srcB);
                float a3 = oddc ? s7 : s6;
                uint4 H, L;
                tf32_split(a0, H.x, L.x);
                tf32_split(a1, H.y, L.y);
                tf32_split(a2, H.z, L.z);
                tf32_split(a3, H.w, L.w);
                int ix = (warpM * 2 + m) * 32 + lane;
                sAh[0][ix] = H;
                sAl[0][ix] = L;
            }
        }
        __syncthreads();

        uint4 ah[2], al[2];
#pragma unroll
        for (int m = 0; m < 2; m++) {
            int ix = (warpM * 2 + m) * 32 + lane;
            ah[m] = sAh[0][ix];
            al[m] = sAl[0][ix];
        }
#pragma unroll
        for (int t2 = 0; t2 < 4; t2++) {
            int nt = warpN * 4 + t2;
            uint2 bh = B3H[(kc * 8 + nt) * 32 + lane];
            uint2 bl = B3L[(kc * 8 + nt) * 32 + lane];
#pragma unroll
            for (int m = 0; m < 2; m++) {
                mma_tf32(oacc[m][t2], (const uint32_t*)&al[m],
                         (const uint32_t*)&bh);
                mma_tf32(oacc[m][t2], (const uint32_t*)&ah[m],
                         (const uint32_t*)&bl);
                mma_tf32(oacc[m][t2], (const uint32_t*)&ah[m],
                         (const uint32_t*)&bh);
            }
        }
        __syncthreads();
    }

    // out epilogue (M=64)
#pragma unroll
    for (int m = 0; m < 2; m++) {
#pragma unroll
        for (int t2 = 0; t2 < 4; t2++) {
            int row = (mtb + warpM * 2 + m) * 16 + g;
            int col = (warpN * 4 + t2) * 8 + tig * 2;
            float b0 = bias3[col], b1 = bias3[col + 1];
            float d0 = oacc[m][t2][0] + b0, d1 = oacc[m][t2][1] + b1;
            float d2 = oacc[m][t2][2] + b0, d3 = oacc[m][t2][3] + b1;
            if (row < n)
                *(float2*)(out + (size_t)row * 64 + col) = make_float2(d0, d1);
            if (row + 8 < n)
                *(float2*)(out + (size_t)(row + 8) * 64 + col) =
                    make_float2(d2, d3);
        }
    }
}

// ---------------- CSR scan / scatter -----------------------------------------
__global__ __launch_bounds__(1024) void scan1_kernel(int n)
{
    __shared__ int wsum[32];
    int tid = threadIdx.x, lane = tid & 31, wid = tid >> 5;
    int idx = blockIdx.x * 1024 + tid;
    int v = (idx < n) ? g_hist[idx] : 0;
    int x = v;
#pragma unroll
    for (int o = 1; o < 32; o <<= 1) {
        int y = __shfl_up_sync(0xffffffffu, x, o);
        if (lane >= o) x += y;
    }
    if (lane == 31) wsum[wid] = x;
    __syncthreads();
    if (wid == 0) {
        int t = wsum[lane];
#pragma unroll
        for (int o = 1; o < 32; o <<= 1) {
            int y = __shfl_up_sync(0xffffffffu, t, o);
            if (lane >= o) t += y;
        }
        wsum[lane] = t;
    }
    __syncthreads();
    int pre = (wid > 0) ? wsum[wid - 1] : 0;
    if (idx < n) g_rowstart[idx] = pre + (x - v);
    if (tid == 0) g_bsum[blockIdx.x] = wsum[31];
}

__global__ void scan2_kernel(int nblk, int n)
{
    int lane = threadIdx.x;
    int c = 0;
    for (int base = 0; base < nblk; base += 32) {
        int v = (base + lane < nblk) ? g_bsum[base + lane] : 0;
        int x = v;
#pragma unroll
        for (int o = 1; o < 32; o <<= 1) {
            int y = __shfl_up_sync(0xffffffffu, x, o);
            if (lane >= o) x += y;
        }
        if (base + lane < nblk) g_boff[base + lane] = c + (x - v);
        c += __shfl_sync(0xffffffffu, x, 31);
    }
    if (lane == 0) g_rowstart[n] = c;
}

__global__ void scan3_kernel(int n)
{
    int idx = blockIdx.x * blockDim.x + threadIdx.x;
    if (idx < n) {
        g_rowstart[idx] += g_boff[idx >> 10];
        g_hist[idx] = 0;     // self-clean for next replay
    }
}

__global__ void scatter_kernel(const void* __restrict__ ei, int E, int et, int n)
{
    int e = blockIdx.x * blockDim.x + threadIdx.x;
    if (e >= et) return;
    int s, d;
    if (e < E) {
        s = edge_at(ei, e);
        d = edge_at(ei, (long long)E + e);
    } else {
        s = d = e - E;
    }
    s = min(max(s, 0), n - 1);
    d = min(max(d, 0), n - 1);
    int pos = g_rowstart[d] + atomicAdd(&g_cnt[d], 1);
    g_es[pos] = s;
}

// ---------------- pull-style GATv2 softmax aggregation ----------------------
__global__ void agg_kernel(const float* __restrict__ att,
                           const float* __restrict__ bg, int n)
{
    int w    = (blockIdx.x * blockDim.x + threadIdx.x) >> 5;
    int lane = threadIdx.x & 31;
    if (w >= n) return;

    int beg = g_rowstart[w], end = g_rowstart[w + 1];
    const float4* xl4 = (const float4*)g_xl;
    float4 xrv = ((const float4*)g_xr)[(size_t)w * 32 + lane];
    float4 atv = ((const float4*)att)[lane];

    float denom = 0.f;
    float4 acc = make_float4(0.f, 0.f, 0.f, 0.f);

    int p = beg;
    for (; p + 3 < end; p += 4) {
        int s0 = __ldg(&g_es[p]);
        int s1 = __ldg(&g_es[p + 1]);
        int s2 = __ldg(&g_es[p + 2]);
        int s3 = __ldg(&g_es[p + 3]);
        float4 x0 = xl4[(size_t)s0 * 32 + lane];
        float4 x1 = xl4[(size_t)s1 * 32 + lane];
        float4 x2 = xl4[(size_t)s2 * 32 + lane];
        float4 x3 = xl4[(size_t)s3 * 32 + lane];
        float v0 = lrelu(x0.x + xrv.x) * atv.x + lrelu(x0.y + xrv.y) * atv.y
                 + lrelu(x0.z + xrv.z) * atv.z + lrelu(x0.w + xrv.w) * atv.w;
        float v1 = lrelu(x1.x + xrv.x) * atv.x + lrelu(x1.y + xrv.y) * atv.y
                 + lrelu(x1.z + xrv.z) * atv.z + lrelu(x1.w + xrv.w) * atv.w;
        float v2 = lrelu(x2.x + xrv.x) * atv.x + lrelu(x2.y + xrv.y) * atv.y
                 + lrelu(x2.z + xrv.z) * atv.z + lrelu(x2.w + xrv.w) * atv.w;
        float v3 = lrelu(x3.x + xrv.x) * atv.x + lrelu(x3.y + xrv.y) * atv.y
                 + lrelu(x3.z + xrv.z) * atv.z + lrelu(x3.w + xrv.w) * atv.w;
        v0 = warp_sum(v0);
        v1 = warp_sum(v1);
        v2 = warp_sum(v2);
        v3 = warp_sum(v3);
        float e0 = __expf(v0), e1 = __expf(v1);
        float e2 = __expf(v2), e3 = __expf(v3);
        denom += (e0 + e1) + (e2 + e3);
        acc.x += e0 * x0.x + e1 * x1.x + e2 * x2.x + e3 * x3.x;
        acc.y += e0 * x0.y + e1 * x1.y + e2 * x2.y + e3 * x3.y;
        acc.z += e0 * x0.z + e1 * x1.z + e2 * x2.z + e3 * x3.z;
        acc.w += e0 * x0.w + e1 * x1.w + e2 * x2.w + e3 * x3.w;
    }
    for (; p < end; p++) {
        int s0 = __ldg(&g_es[p]);
        float4 x0 = xl4[(size_t)s0 * 32 + lane];
        float v0 = lrelu(x0.x + xrv.x) * atv.x + lrelu(x0.y + xrv.y) * atv.y
                 + lrelu(x0.z + xrv.z) * atv.z + lrelu(x0.w + xrv.w) * atv.w;
        v0 = warp_sum(v0);
        float e0 = __expf(v0);
        denom += e0;
        acc.x += e0 * x0.x; acc.y += e0 * x0.y;
        acc.z += e0 * x0.z; acc.w += e0 * x0.w;
    }

    float inv = 1.f / denom;
    float4 bgv = ((const float4*)bg)[lane];
    float4 hv = make_float4(acc.x * inv + bgv.x, acc.y * inv + bgv.y,
                            acc.z * inv + bgv.z, acc.w * inv + bgv.w);
    ((float4*)g_h)[(size_t)w * 32 + lane] = hv;
    if (lane == 0) g_cnt[w] = 0;   // self-clean for next replay
}

// ---------------- launch -----------------------------------------------------
extern "C" void kernel_launch(void* const* d_in, const int* in_sizes, int n_in,
                              void* d_out, int out_size)
{
    (void)n_in; (void)out_size;
    const float* x   = (const float*)d_in[0];
    const void*  ei  = d_in[1];
    const float* Wl  = (const float*)d_in[2];
    const float* bl  = (const float*)d_in[3];
    const float* Wr  = (const float*)d_in[4];
    const float* br  = (const float*)d_in[5];
    const float* att = (const float*)d_in[6];
    const float* bg  = (const float*)d_in[7];
    const float* W1  = (const float*)d_in[8];
    const float* b1  = (const float*)d_in[9];
    const float* W2  = (const float*)d_in[10];
    const float* b2  = (const float*)d_in[11];
    const float* W3  = (const float*)d_in[12];
    const float* b3  = (const float*)d_in[13];
    float* out = (float*)d_out;

    const int n  = in_sizes[0] / DIN_;       // 50000
    const int E  = in_sizes[1] / 2;          // 800000
    const int et = E + n;
    const int gm   = (n + 127) / 128;        // 391
    const int sblk = (n + 1023) / 1024;
    const int hb   = (et + 255) / 256;       // histogram blocks

    wconv_all<<<73, 256>>>(Wl, Wr, W1, W2, W3,
                           (const unsigned long long*)ei, 4096);
    aconv_kernel<1><<<MT_PAD + hb, 256>>>(x, n, ei, E, et);   // conv + hist

    gemm_xlr<<<2 * gm, 256>>>(bl, br, gm, n);

    scan1_kernel<<<sblk, 1024>>>(n);
    scan2_kernel<<<1, 32>>>(sblk, n);
    scan3_kernel<<<(n + 255) / 256, 256>>>(n);
    scatter_kernel<<<(et + 255) / 256, 256>>>(ei, E, et, n);
    agg_kernel<<<(n * 32 + 255) / 256, 256>>>(att, bg, n);

    aconv_kernel<2><<<MT_PAD, 256>>>(nullptr, n, nullptr, 0, 0);
    gemm_h1<<<gm, 256>>>(b1, 16384, n);          // h  -> h1 frags
    gemm_h2out<<<gm, 256>>>(out, b2, b3, n);     // h1 -> h2 -> out (fused)
}

// round 16
// speedup vs baseline: 1.1502x; 1.1502x over previous
#include <cuda_runtime.h>
#include <cstdint>

#define NN    50000
#define EE    800000
#define ETOT  (EE + NN)
#define DIN_  128
#define MT_PAD 3128                 // ceil(50000/16) 16-row tiles
#define KC16   16                   // K/8 k-chunks
#define AWORDS (MT_PAD * KC16 * 32) // uint4 count per frag matrix

// ---------------- scratch (device globals: no runtime allocation) ----------
__device__ float g_xl[(size_t)NN * DIN_];
__device__ float g_xr[(size_t)NN * DIN_];
__device__ float g_h [(size_t)NN * DIN_];
__device__ int   g_es[ETOT];
__device__ int   g_hist[NN];
__device__ int   g_cnt[NN];
__device__ int   g_rowstart[NN + 1];
__device__ int   g_bsum[64];
__device__ int   g_boff[64];
__device__ int   g_is32;

// fragment-major tf32 hi/lo A buffers: uint4 at ((mt*16 + kc)*32 + lane)
__device__ uint4 g_xfh[AWORDS],  g_xfl[AWORDS];    // x
__device__ uint4 g_hfh[AWORDS],  g_hfl[AWORDS];    // h   (aconv<2>)
__device__ uint4 g_h1fh[AWORDS], g_h1fl[AWORDS];   // h1  (epilogue-emitted)
__device__ uint4 g_h2fh[AWORDS], g_h2fl[AWORDS];   // h2  (epilogue-emitted)
// fragment-major tf32 weights: uint2 at woff + (kc*NT + nt)*32 + lane
// Wl=0, Wr=8192, W1=16384, W2=24576, W3=32768
__device__ uint2 g_wfh[36864], g_wfl[36864];

__device__ __forceinline__ const uint4* abuf_h(int id) {
    switch (id) { case 2: return g_hfh; case 3: return g_h1fh;
                  default: return g_h2fh; }
}
__device__ __forceinline__ const uint4* abuf_l(int id) {
    switch (id) { case 2: return g_hfl; case 3: return g_h1fl;
                  default: return g_h2fl; }
}
__device__ __forceinline__ uint4* afrag_h(int id) {
    switch (id) { case 3: return g_h1fh; default: return g_h2fh; }
}
__device__ __forceinline__ uint4* afrag_l(int id) {
    switch (id) { case 3: return g_h1fl; default: return g_h2fl; }
}

// ---------------- helpers ----------------------------------------------------
__device__ __forceinline__ float lrelu(float v) { return v > 0.f ? v : 0.2f * v; }

__device__ __forceinline__ float warp_sum(float v) {
#pragma unroll
    for (int o = 16; o > 0; o >>= 1) v += __shfl_xor_sync(0xffffffffu, v, o);
    return v;
}

__device__ __forceinline__ int edge_at(const void* ei, long long idx) {
    if (g_is32) return ((const int*)ei)[idx];
    return (int)((const long long*)ei)[idx];
}

__device__ __forceinline__ uint32_t f2tf32(float x) {
    uint32_t r;
    asm("cvt.rna.tf32.f32 %0, %1;" : "=r"(r) : "f"(x));
    return r;
}
__device__ __forceinline__ void tf32_split(float x, uint32_t& hi, uint32_t& lo) {
    hi = f2tf32(x);
    lo = f2tf32(x - __uint_as_float(hi));
}

__device__ __forceinline__ void mma_tf32(float* d, const uint32_t* a,
                                         const uint32_t* b) {
    asm volatile(
        "mma.sync.aligned.m16n8k8.row.col.f32.tf32.tf32.f32 "
        "{%0,%1,%2,%3}, {%4,%5,%6,%7}, {%8,%9}, {%0,%1,%2,%3};"
        : "+f"(d[0]), "+f"(d[1]), "+f"(d[2]), "+f"(d[3])
        : "r"(a[0]), "r"(a[1]), "r"(a[2]), "r"(a[3]), "r"(b[0]), "r"(b[1]));
}

__device__ __forceinline__ void cp_async16(uint32_t dst, const void* src) {
    asm volatile("cp.async.cg.shared.global [%0], [%1], 16;"
                 :: "r"(dst), "l"(src));
}
__device__ __forceinline__ void cp_commit() {
    asm volatile("cp.async.commit_group;");
}
__device__ __forceinline__ void cp_wait0() {
    asm volatile("cp.async.wait_group 0;");
}
__device__ __forceinline__ void cp_wait1() {
    asm volatile("cp.async.wait_group 1;");
}

// ---------------- all-weights convert + edge dtype detect (one launch) ------
__global__ void wconv_all(const float* __restrict__ Wl,
                          const float* __restrict__ Wr,
                          const float* __restrict__ W1,
                          const float* __restrict__ W2,
                          const float* __restrict__ W3,
                          const unsigned long long* __restrict__ ei, int m)
{
    int bx = blockIdx.x;
    if (bx == 72) {   // edge dtype detection (independent block)
        __shared__ int found;
        if (threadIdx.x == 0) found = 0;
        __syncthreads();
        for (int i = threadIdx.x; i < m; i += blockDim.x)
            if ((ei[i] >> 32) != 0ull) found = 1;
        __syncthreads();
        if (threadIdx.x == 0) g_is32 = found;
        return;
    }
    const float* W;
    int woff, nt, M = 128;
    if      (bx < 16) { W = Wl; woff = 0;     nt = bx; }
    else if (bx < 32) { W = Wr; woff = 8192;  nt = bx - 16; }
    else if (bx < 48) { W = W1; woff = 16384; nt = bx - 32; }
    else if (bx < 64) { W = W2; woff = 24576; nt = bx - 48; }
    else              { W = W3; woff = 32768; nt = bx - 64; M = 64; }
    int NT = M / 8;
    int tid = threadIdx.x;
    int w8 = tid >> 5, lane = tid & 31, g = lane >> 2, tig = lane & 3;
    int ncol = nt * 8 + g;
#pragma unroll
    for (int j = 0; j < 2; j++) {
        int kc = w8 + j * 8;
        int k0 = kc * 8 + tig;
        float w0 = W[(size_t)k0 * M + ncol];
        float w1 = W[(size_t)(k0 + 4) * M + ncol];
        uint32_t h0, l0, h1, l1;
        tf32_split(w0, h0, l0);
        tf32_split(w1, h1, l1);
        int ix = woff + (kc * NT + nt) * 32 + lane;
        g_wfh[ix] = make_uint2(h0, h1);
        g_wfl[ix] = make_uint2(l0, l1);
    }
}

// ---------------- activation convert: X[n][128] -> tf32 A-fragments ---------
template<int SRC>   // 1 = x param -> xf, 2 = g_h -> hf
__global__ __launch_bounds__(256)
void aconv_kernel(const float* __restrict__ Xp, int n)
{
    const float* X = (SRC == 1) ? Xp : g_h;
    __shared__ float s[16 * 132];
    int mt = blockIdx.x;
    int tid = threadIdx.x;
#pragma unroll
    for (int j = 0; j < 2; j++) {
        int f = tid + j * 256;
        int row = f >> 5;
        int q = f & 31;
        int r = mt * 16 + row;
        float4 v = (r < n) ? *(const float4*)(X + (size_t)r * 128 + q * 4)
                           : make_float4(0.f, 0.f, 0.f, 0.f);
        *(float4*)&s[row * 132 + q * 4] = v;
    }
    __syncthreads();

    int w8 = tid >> 5, lane = tid & 31, g = lane >> 2, tig = lane & 3;
    uint4* OH = (SRC == 1) ? g_xfh : g_hfh;
    uint4* OL = (SRC == 1) ? g_xfl : g_hfl;
#pragma unroll
    for (int j = 0; j < 2; j++) {
        int kc = w8 + j * 8;
        int c0 = kc * 8 + tig, c1 = c0 + 4;
        float p0 = s[g * 132 + c0];
        float p1 = s[(g + 8) * 132 + c0];
        float p2 = s[g * 132 + c1];
        float p3 = s[(g + 8) * 132 + c1];
        uint4 H, L;
        tf32_split(p0, H.x, L.x);
        tf32_split(p1, H.y, L.y);
        tf32_split(p2, H.z, L.z);
        tf32_split(p3, H.w, L.w);
        int ix = (mt * KC16 + kc) * 32 + lane;
        OH[ix] = H;
        OL[ix] = L;
    }
}

// ---------------- fused xl+xr GEMM (2-stage, tail-merged; R14-validated) ----
__global__ __launch_bounds__(256)
void gemm_xlr(const float* __restrict__ bl, const float* __restrict__ br,
              int gm, int n)
{
    constexpr int NT = 16, NTW = 8, B4 = 256;

    const bool isR = blockIdx.x >= gm;
    const int  bx  = isR ? (blockIdx.x - gm) : blockIdx.x;
    const int  woff = isR ? 8192 : 0;
    float* out = isR ? g_xr : g_xl;
    const float* bias = isR ? br : bl;

    const uint4* AH = g_xfh;
    const uint4* AL = g_xfl;
    const uint2* BH = g_wfh + woff;
    const uint2* BL = g_wfl + woff;

    __shared__ uint4 sAh[2][256], sAl[2][256];
    __shared__ uint4 sBh[2][B4],  sBl[2][B4];

    const int tid   = threadIdx.x;
    const int lane  = tid & 31;
    const int wid   = tid >> 5;
    const int warpM = wid & 3;
    const int warpN = wid >> 2;
    const int mtb   = bx * 8;

    const int a_mt = tid >> 5;
    const int a_ln = tid & 31;

#define ISSUE_STAGE(KC_, BUF_)                                                  \
    do {                                                                        \
        int _src = ((mtb + a_mt) * KC16 + (KC_)) * 32 + a_ln;                  \
        cp_async16((uint32_t)__cvta_generic_to_shared(&sAh[BUF_][tid]),        \
                   AH + _src);                                                  \
        cp_async16((uint32_t)__cvta_generic_to_shared(&sAl[BUF_][tid]),        \
                   AL + _src);                                                  \
        const uint4* _bh = (const uint4*)(BH + (size_t)(KC_) * NT * 32);       \
        const uint4* _bl = (const uint4*)(BL + (size_t)(KC_) * NT * 32);       \
        cp_async16((uint32_t)__cvta_generic_to_shared(&sBh[BUF_][tid]),        \
                   _bh + tid);                                                  \
        cp_async16((uint32_t)__cvta_generic_to_shared(&sBl[BUF_][tid]),        \
                   _bl + tid);                                                  \
        cp_commit();                                                            \
    } while (0)

    float acc[2][NTW][4];
#pragma unroll
    for (int m = 0; m < 2; m++)
#pragma unroll
        for (int t = 0; t < NTW; t++)
#pragma unroll
            for (int i = 0; i < 4; i++) acc[m][t][i] = 0.f;

    ISSUE_STAGE(0, 0);

#pragma unroll 2
    for (int kc = 0; kc < KC16; kc++) {
        const int buf = kc & 1;
        if (kc + 1 < KC16) {
            ISSUE_STAGE(kc + 1, buf ^ 1);
            cp_wait1();
        } else {
            cp_wait0();
        }
        __syncthreads();

        uint4 ah[2], al[2];
#pragma unroll
        for (int m = 0; m < 2; m++) {
            int ix = (warpM * 2 + m) * 32 + lane;
            ah[m] = sAh[buf][ix];
            al[m] = sAl[buf][ix];
        }
        const uint2* b2h = (const uint2*)sBh[buf];
        const uint2* b2l = (const uint2*)sBl[buf];
#pragma unroll
        for (int t = 0; t < NTW; t++) {
            int nt = warpN * NTW + t;
            uint2 bh = b2h[nt * 32 + lane];
            uint2 bl2 = b2l[nt * 32 + lane];
#pragma unroll
            for (int m = 0; m < 2; m++) {
                mma_tf32(acc[m][t], (const uint32_t*)&al[m],
                         (const uint32_t*)&bh);
                mma_tf32(acc[m][t], (const uint32_t*)&ah[m],
                         (const uint32_t*)&bl2);
                mma_tf32(acc[m][t], (const uint32_t*)&ah[m],
                         (const uint32_t*)&bh);
            }
        }
        __syncthreads();
    }
#undef ISSUE_STAGE

    const int g   = lane >> 2;
    const int tig = lane & 3;
#pragma unroll
    for (int m = 0; m < 2; m++) {
#pragma unroll
        for (int t = 0; t < NTW; t++) {
            int row = (mtb + warpM * 2 + m) * 16 + g;
            int col = (warpN * NTW + t) * 8 + tig * 2;
            float b0 = bias[col], b1 = bias[col + 1];
            float d0 = acc[m][t][0] + b0, d1 = acc[m][t][1] + b1;
            float d2 = acc[m][t][2] + b0, d3 = acc[m][t][3] + b1;
            if (row < n)
                *(float2*)(out + (size_t)row * 128 + col) = make_float2(d0, d1);
            if (row + 8 < n)
                *(float2*)(out + (size_t)(row + 8) * 128 + col) =
                    make_float2(d2, d3);
        }
    }
}

// ---------------- frag-GEMM (tf32 3-split, cp.async 2-stage, y-collapsed) ---
// OID: 0 -> fp32 param; 3 -> h1 frag, 4 -> h2 frag (shuffle emission)
template<int M, bool RELU, int AID, int OID>
__global__ __launch_bounds__(256)
void gemm_frag(float* __restrict__ xout, const float* __restrict__ bias,
               int woff, int n)
{
    constexpr int NT  = M / 8;
    constexpr int NTW = NT / 2;
    constexpr int B4  = NT * 16;

    const uint4* AH = abuf_h(AID);
    const uint4* AL = abuf_l(AID);
    const uint2* BH = g_wfh + woff;
    const uint2* BL = g_wfl + woff;

    __shared__ uint4 sAh[2][256], sAl[2][256];
    __shared__ uint4 sBh[2][B4],  sBl[2][B4];

    const int tid   = threadIdx.x;
    const int lane  = tid & 31;
    const int wid   = tid >> 5;
    const int warpM = wid & 3;
    const int warpN = wid >> 2;
    const int mtb   = blockIdx.x * 8;

    const int a_mt = tid >> 5;
    const int a_ln = tid & 31;

#define ISSUE_STAGE(KC_, BUF_)                                                  \
    do {                                                                        \
        int _src = ((mtb + a_mt) * KC16 + (KC_)) * 32 + a_ln;                  \
        cp_async16((uint32_t)__cvta_generic_to_shared(&sAh[BUF_][tid]),        \
                   AH + _src);                                                  \
        cp_async16((uint32_t)__cvta_generic_to_shared(&sAl[BUF_][tid]),        \
                   AL + _src);                                                  \
        const uint4* _bh = (const uint4*)(BH + (size_t)(KC_) * NT * 32);       \
        const uint4* _bl = (const uint4*)(BL + (size_t)(KC_) * NT * 32);       \
        for (int _i = tid; _i < B4; _i += 256) {                               \
            cp_async16((uint32_t)__cvta_generic_to_shared(&sBh[BUF_][_i]),     \
                       _bh + _i);                                               \
            cp_async16((uint32_t)__cvta_generic_to_shared(&sBl[BUF_][_i]),     \
                       _bl + _i);                                               \
        }                                                                       \
        cp_commit();                                                            \
    } while (0)

    float acc[2][NTW][4];
#pragma unroll
    for (int m = 0; m < 2; m++)
#pragma unroll
        for (int t = 0; t < NTW; t++)
#pragma unroll
            for (int i = 0; i < 4; i++) acc[m][t][i] = 0.f;

    ISSUE_STAGE(0, 0);

#pragma unroll 2
    for (int kc = 0; kc < KC16; kc++) {
        const int buf = kc & 1;
        if (kc + 1 < KC16) {
            ISSUE_STAGE(kc + 1, buf ^ 1);
            cp_wait1();
        } else {
            cp_wait0();
        }
        __syncthreads();

        uint4 ah[2], al[2];
#pragma unroll
        for (int m = 0; m < 2; m++) {
            int ix = (warpM * 2 + m) * 32 + lane;
            ah[m] = sAh[buf][ix];
            al[m] = sAl[buf][ix];
        }
        const uint2* b2h = (const uint2*)sBh[buf];
        const uint2* b2l = (const uint2*)sBl[buf];
#pragma unroll
        for (int t = 0; t < NTW; t++) {
            int nt = warpN * NTW + t;
            uint2 bh = b2h[nt * 32 + lane];
            uint2 bl = b2l[nt * 32 + lane];
#pragma unroll
            for (int m = 0; m < 2; m++) {
                mma_tf32(acc[m][t], (const uint32_t*)&al[m],
                         (const uint32_t*)&bh);
                mma_tf32(acc[m][t], (const uint32_t*)&ah[m],
                         (const uint32_t*)&bl);
                mma_tf32(acc[m][t], (const uint32_t*)&ah[m],
                         (const uint32_t*)&bh);
            }
        }
        __syncthreads();
    }
#undef ISSUE_STAGE

    const int g   = lane >> 2;
    const int tig = lane & 3;

    if (OID == 0) {
        float* out = xout;
#pragma unroll
        for (int m = 0; m < 2; m++) {
#pragma unroll
            for (int t = 0; t < NTW; t++) {
                int row = (mtb + warpM * 2 + m) * 16 + g;
                int col = (warpN * NTW + t) * 8 + tig * 2;
                float b0 = bias[col], b1 = bias[col + 1];
                float d0 = acc[m][t][0] + b0, d1 = acc[m][t][1] + b1;
                float d2 = acc[m][t][2] + b0, d3 = acc[m][t][3] + b1;
                if (RELU) {
                    d0 = fmaxf(d0, 0.f); d1 = fmaxf(d1, 0.f);
                    d2 = fmaxf(d2, 0.f); d3 = fmaxf(d3, 0.f);
                }
                if (row < n)
                    *(float2*)(out + (size_t)row * M + col) = make_float2(d0, d1);
                if (row + 8 < n)
                    *(float2*)(out + (size_t)(row + 8) * M + col) =
                        make_float2(d2, d3);
            }
        }
    } else {
        // frag-direct emission (R10-validated intra-warp permutation)
        uint4* OH = afrag_h(OID);
        uint4* OL = afrag_l(OID);
        const int srcA = (lane & ~3) + (tig >> 1);
        const int srcB = srcA + 2;
        const bool oddc = (tig & 1) != 0;
#pragma unroll
        for (int m = 0; m < 2; m++) {
            int mtg = mtb + warpM * 2 + m;
#pragma unroll
            for (int t = 0; t < NTW; t++) {
                int kc  = warpN * NTW + t;
                int col = kc * 8 + tig * 2;
                float b0 = bias[col], b1 = bias[col + 1];
                float d0 = acc[m][t][0] + b0, d1 = acc[m][t][1] + b1;
                float d2 = acc[m][t][2] + b0, d3 = acc[m][t][3] + b1;
                if (RELU) {
                    d0 = fmaxf(d0, 0.f); d1 = fmaxf(d1, 0.f);
                    d2 = fmaxf(d2, 0.f); d3 = fmaxf(d3, 0.f);
                }
                float s0 = __shfl_sync(0xffffffffu, d0, srcA);
                float s1 = __shfl_sync(0xffffffffu, d1, srcA);
                float a0 = oddc ? s1 : s0;
                float s2 = __shfl_sync(0xffffffffu, d2, srcA);
                float s3 = __shfl_sync(0xffffffffu, d3, srcA);
                float a1 = oddc ? s3 : s2;
                float s4 = __shfl_sync(0xffffffffu, d0, srcB);
                float s5 = __shfl_sync(0xffffffffu, d1, srcB);
                float a2 = oddc ? s5 : s4;
                float s6 = __shfl_sync(0xffffffffu, d2, srcB);
                float s7 = __shfl_sync(0xffffffffu, d3, srcB);
                float a3 = oddc ? s7 : s6;
                uint4 H, L;
                tf32_split(a0, H.x, L.x);
                tf32_split(a1, H.y, L.y);
                tf32_split(a2, H.z, L.z);
                tf32_split(a3, H.w, L.w);
                int ix = (mtg * KC16 + kc) * 32 + lane;
                OH[ix] = H;
                OL[ix] = L;
            }
        }
    }
}

// ---------------- CSR construction ------------------------------------------
__global__ void hist_kernel(const void* __restrict__ ei, int E, int et, int n)
{
    int e = blockIdx.x * blockDim.x + threadIdx.x;
    if (e >= et) return;
    int d = (e < E) ? edge_at(ei, (long long)E + e) : (e - E);
    d = min(max(d, 0), n - 1);
    atomicAdd(&g_hist[d], 1);
}

__global__ __launch_bounds__(1024) void scan1_kernel(int n)
{
    __shared__ int wsum[32];
    int tid = threadIdx.x, lane = tid & 31, wid = tid >> 5;
    int idx = blockIdx.x * 1024 + tid;
    int v = (idx < n) ? g_hist[idx] : 0;
    int x = v;
#pragma unroll
    for (int o = 1; o < 32; o <<= 1) {
        int y = __shfl_up_sync(0xffffffffu, x, o);
        if (lane >= o) x += y;
    }
    if (lane == 31) wsum[wid] = x;
    __syncthreads();
    if (wid == 0) {
        int t = wsum[lane];
#pragma unroll
        for (int o = 1; o < 32; o <<= 1) {
            int y = __shfl_up_sync(0xffffffffu, t, o);
            if (lane >= o) t += y;
        }
        wsum[lane] = t;
    }
    __syncthreads();
    int pre = (wid > 0) ? wsum[wid - 1] : 0;
    if (idx < n) g_rowstart[idx] = pre + (x - v);
    if (tid == 0) g_bsum[blockIdx.x] = wsum[31];
}

__global__ void scan2_kernel(int nblk, int n)
{
    int lane = threadIdx.x;
    int c = 0;
    for (int base = 0; base < nblk; base += 32) {
        int v = (base + lane < nblk) ? g_bsum[base + lane] : 0;
        int x = v;
#pragma unroll
        for (int o = 1; o < 32; o <<= 1) {
            int y = __shfl_up_sync(0xffffffffu, x, o);
            if (lane >= o) x += y;
        }
        if (base + lane < nblk) g_boff[base + lane] = c + (x - v);
        c += __shfl_sync(0xffffffffu, x, 31);
    }
    if (lane == 0) g_rowstart[n] = c;
}

// phase 3 also re-zeros g_hist for the NEXT invocation (graph replays)
__global__ void scan3_kernel(int n)
{
    int idx = blockIdx.x * blockDim.x + threadIdx.x;
    if (idx < n) {
        g_rowstart[idx] += g_boff[idx >> 10];
        g_hist[idx] = 0;
    }
}

__global__ void scatter_kernel(const void* __restrict__ ei, int E, int et, int n)
{
    int e = blockIdx.x * blockDim.x + threadIdx.x;
    if (e >= et) return;
    int s, d;
    if (e < E) {
        s = edge_at(ei, e);
        d = edge_at(ei, (long long)E + e);
    } else {
        s = d = e - E;
    }
    s = min(max(s, 0), n - 1);
    d = min(max(d, 0), n - 1);
    int pos = g_rowstart[d] + atomicAdd(&g_cnt[d], 1);
    g_es[pos] = s;
}

// ---------------- pull-style GATv2 softmax aggregation ----------------------
// coalesced fp32 h output (R10-validated); re-zeros g_cnt for next replay.
__global__ void agg_kernel(const float* __restrict__ att,
                           const float* __restrict__ bg, int n)
{
    int w    = (blockIdx.x * blockDim.x + threadIdx.x) >> 5;
    int lane = threadIdx.x & 31;
    if (w >= n) return;

    int beg = g_rowstart[w], end = g_rowstart[w + 1];
    const float4* xl4 = (const float4*)g_xl;
    float4 xrv = ((const float4*)g_xr)[(size_t)w * 32 + lane];
    float4 atv = ((const float4*)att)[lane];

    float denom = 0.f;
    float4 acc = make_float4(0.f, 0.f, 0.f, 0.f);

    int p = beg;
    for (; p + 3 < end; p += 4) {
        int s0 = __ldg(&g_es[p]);
        int s1 = __ldg(&g_es[p + 1]);
        int s2 = __ldg(&g_es[p + 2]);
        int s3 = __ldg(&g_es[p + 3]);
        float4 x0 = xl4[(size_t)s0 * 32 + lane];
        float4 x1 = xl4[(size_t)s1 * 32 + lane];
        float4 x2 = xl4[(size_t)s2 * 32 + lane];
        float4 x3 = xl4[(size_t)s3 * 32 + lane];
        float v0 = lrelu(x0.x + xrv.x) * atv.x + lrelu(x0.y + xrv.y) * atv.y
                 + lrelu(x0.z + xrv.z) * atv.z + lrelu(x0.w + xrv.w) * atv.w;
        float v1 = lrelu(x1.x + xrv.x) * atv.x + lrelu(x1.y + xrv.y) * atv.y
                 + lrelu(x1.z + xrv.z) * atv.z + lrelu(x1.w + xrv.w) * atv.w;
        float v2 = lrelu(x2.x + xrv.x) * atv.x + lrelu(x2.y + xrv.y) * atv.y
                 + lrelu(x2.z + xrv.z) * atv.z + lrelu(x2.w + xrv.w) * atv.w;
        float v3 = lrelu(x3.x + xrv.x) * atv.x + lrelu(x3.y + xrv.y) * atv.y
                 + lrelu(x3.z + xrv.z) * atv.z + lrelu(x3.w + xrv.w) * atv.w;
        v0 = warp_sum(v0);
        v1 = warp_sum(v1);
        v2 = warp_sum(v2);
        v3 = warp_sum(v3);
        float e0 = __expf(v0), e1 = __expf(v1);
        float e2 = __expf(v2), e3 = __expf(v3);
        denom += (e0 + e1) + (e2 + e3);
        acc.x += e0 * x0.x + e1 * x1.x + e2 * x2.x + e3 * x3.x;
        acc.y += e0 * x0.y + e1 * x1.y + e2 * x2.y + e3 * x3.y;
        acc.z += e0 * x0.z + e1 * x1.z + e2 * x2.z + e3 * x3.z;
        acc.w += e0 * x0.w + e1 * x1.w + e2 * x2.w + e3 * x3.w;
    }
    for (; p < end; p++) {
        int s0 = __ldg(&g_es[p]);
        float4 x0 = xl4[(size_t)s0 * 32 + lane];
        float v0 = lrelu(x0.x + xrv.x) * atv.x + lrelu(x0.y + xrv.y) * atv.y
                 + lrelu(x0.z + xrv.z) * atv.z + lrelu(x0.w + xrv.w) * atv.w;
        v0 = warp_sum(v0);
        float e0 = __expf(v0);
        denom += e0;
        acc.x += e0 * x0.x; acc.y += e0 * x0.y;
        acc.z += e0 * x0.z; acc.w += e0 * x0.w;
    }

    float inv = 1.f / denom;
    float4 bgv = ((const float4*)bg)[lane];
    float4 hv = make_float4(acc.x * inv + bgv.x, acc.y * inv + bgv.y,
                            acc.z * inv + bgv.z, acc.w * inv + bgv.w);
    ((float4*)g_h)[(size_t)w * 32 + lane] = hv;
    if (lane == 0) g_cnt[w] = 0;   // self-clean for next replay
}

// ---------------- launch -----------------------------------------------------
extern "C" void kernel_launch(void* const* d_in, const int* in_sizes, int n_in,
                              void* d_out, int out_size)
{
    (void)n_in; (void)out_size;
    const float* x   = (const float*)d_in[0];
    const void*  ei  = d_in[1];
    const float* Wl  = (const float*)d_in[2];
    const float* bl  = (const float*)d_in[3];
    const float* Wr  = (const float*)d_in[4];
    const float* br  = (const float*)d_in[5];
    const float* att = (const float*)d_in[6];
    const float* bg  = (const float*)d_in[7];
    const float* W1  = (const float*)d_in[8];
    const float* b1  = (const float*)d_in[9];
    const float* W2  = (const float*)d_in[10];
    const float* b2  = (const float*)d_in[11];
    const float* W3  = (const float*)d_in[12];
    const float* b3  = (const float*)d_in[13];
    float* out = (float*)d_out;

    const int n  = in_sizes[0] / DIN_;       // 50000
    const int E  = in_sizes[1] / 2;          // 800000
    const int et = E + n;
    const int gm   = (n + 127) / 128;        // 391
    const int sblk = (n + 1023) / 1024;

    wconv_all<<<73, 256>>>(Wl, Wr, W1, W2, W3,
                           (const unsigned long long*)ei, 4096);
    aconv_kernel<1><<<MT_PAD, 256>>>(x, n);

    gemm_xlr<<<2 * gm, 256>>>(bl, br, gm, n);   // fused xl+xr (tail-merged)

    hist_kernel<<<(et + 255) / 256, 256>>>(ei, E, et, n);
    scan1_kernel<<<sblk, 1024>>>(n);
    scan2_kernel<<<1, 32>>>(sblk, n);
    scan3_kernel<<<(n + 255) / 256, 256>>>(n);
    scatter_kernel<<<(et + 255) / 256, 256>>>(ei, E, et, n);
    agg_kernel<<<(n * 32 + 255) / 256, 256>>>(att, bg, n);

    aconv_kernel<2><<<MT_PAD, 256>>>(nullptr, n);
    gemm_frag<128, true, 2, 3><<<gm, 256>>>(nullptr, b1, 16384, n);   // h  -> h1f
    gemm_frag<128, true, 3, 4><<<gm, 256>>>(nullptr, b2, 24576, n);   // h1 -> h2f
    gemm_frag<64, false, 4, 0><<<gm, 256>>>(out, b3, 32768, n);       // h2 -> out
}